// round 8
// baseline (speedup 1.0000x reference)
#include <cuda_runtime.h>
#include <cstdint>

#define NN 12288
#define DD 128
#define JSPLIT 3
#define JLEN (NN / JSPLIT)      // 4096
#define KC 32
#define NC (JLEN / KC)          // 128 chunks
#define MB 128
#define MBLK (NN / MB)          // 96

// dynamic smem layout (floats)
// sP2f[2][128][40] : P pairs (k,k+4) as float2, row pad 40 floats
// sV  [2][32][136]
#define SP_OFF   0
#define SV_OFF   (2 * 128 * 40)
#define DEN_OFF  (SV_OFF + 2 * 32 * 136)
#define SMEM_FLOATS (DEN_OFF + 128)
#define SMEM_BYTES  (SMEM_FLOATS * 4)       // 76288 B

// ---------------- static scratch ----------------
__device__ float g_WT[DD * DD];
__device__ float g_V [(size_t)NN * DD];
__device__ float g_Vr[(size_t)NN * DD];            // tf32-pre-rounded V
__device__ float g_s[NN], g_t[NN];
__device__ float g_Es[NN], g_Et[NN], g_Fs[NN], g_Ft[NN];
__device__ float g_parts[JSPLIT][(size_t)NN * DD];
__device__ float g_dparts[JSPLIT][NN];

__device__ __forceinline__ float totf32(float x) {
    float r; asm("cvt.rna.tf32.f32 %0, %1;" : "=f"(r) : "f"(x)); return r;
}
__device__ __forceinline__ void mma_tf32_16x8x8(float* c, const float* a, const float* b) {
    asm volatile(
        "mma.sync.aligned.m16n8k8.row.col.f32.tf32.tf32.f32 "
        "{%0,%1,%2,%3}, {%4,%5,%6,%7}, {%8,%9}, {%0,%1,%2,%3};"
        : "+f"(c[0]), "+f"(c[1]), "+f"(c[2]), "+f"(c[3])
        : "f"(a[0]), "f"(a[1]), "f"(a[2]), "f"(a[3]), "f"(b[0]), "f"(b[1]));
}
__device__ __forceinline__ void cp_async16(uint32_t dst, const void* src) {
    asm volatile("cp.async.ca.shared.global [%0], [%1], 16;"
                 :: "r"(dst), "l"(src) : "memory");
}
__device__ __forceinline__ void cp_commit() {
    asm volatile("cp.async.commit_group;" ::: "memory");
}
__device__ __forceinline__ void cp_wait0() {
    asm volatile("cp.async.wait_group 0;" ::: "memory");
}
__device__ __forceinline__ void pf_l1(const void* p) {
    asm volatile("prefetch.global.L1 [%0];" :: "l"(p));
}

// ---------------- Kernel A0: transpose W ----------------
__global__ void k_transW(const float* __restrict__ W) {
    int i = blockIdx.x * 256 + threadIdx.x;
    if (i < DD * DD) {
        int d = i >> 7, k = i & 127;
        g_WT[k * DD + d] = W[i];
    }
}

// ---------------- Kernel A: e_new = emb @ W^T (+ tf32-rounded copy) ----------------
__global__ __launch_bounds__(256) void k_enew(const float* __restrict__ emb) {
    const int rb = blockIdx.x * 16;
    const int tid = threadIdx.x;
    __shared__ float es[16][128];
    for (int i = tid; i < 16 * 128; i += 256) {
        int r = i >> 7, k = i & 127;
        es[r][k] = emb[(size_t)(rb + r) * DD + k];
    }
    __syncthreads();
    const int rg = tid >> 5;
    const int dq = tid & 31;
    float acc[2][4];
    #pragma unroll
    for (int i = 0; i < 2; i++)
        #pragma unroll
        for (int j = 0; j < 4; j++) acc[i][j] = 0.f;
    #pragma unroll 4
    for (int k = 0; k < 128; ++k) {
        float4 wv = *(const float4*)&g_WT[k * DD + 4 * dq];
        float e0 = es[rg * 2 + 0][k];
        float e1 = es[rg * 2 + 1][k];
        acc[0][0] += e0 * wv.x; acc[0][1] += e0 * wv.y; acc[0][2] += e0 * wv.z; acc[0][3] += e0 * wv.w;
        acc[1][0] += e1 * wv.x; acc[1][1] += e1 * wv.y; acc[1][2] += e1 * wv.z; acc[1][3] += e1 * wv.w;
    }
    #pragma unroll
    for (int rr = 0; rr < 2; ++rr) {
        size_t row = (size_t)(rb + rg * 2 + rr) * DD;
        *(float4*)&g_V[row + 4 * dq] = make_float4(acc[rr][0], acc[rr][1], acc[rr][2], acc[rr][3]);
        *(float4*)&g_Vr[row + 4 * dq] = make_float4(totf32(acc[rr][0]), totf32(acc[rr][1]),
                                                    totf32(acc[rr][2]), totf32(acc[rr][3]));
    }
}

// ---------------- Kernel B: per-row scalars ----------------
__global__ void k_scal(const float* __restrict__ a) {
    const int i = blockIdx.x;
    const int tid = threadIdx.x;  // 128
    float v = g_V[(size_t)i * DD + tid];
    float sp = v * a[tid];
    float tp = v * a[DD + tid];
    #pragma unroll
    for (int off = 16; off; off >>= 1) {
        sp += __shfl_down_sync(0xffffffffu, sp, off);
        tp += __shfl_down_sync(0xffffffffu, tp, off);
    }
    __shared__ float rs[4], rt[4];
    int w = tid >> 5;
    if ((tid & 31) == 0) { rs[w] = sp; rt[w] = tp; }
    __syncthreads();
    if (tid == 0) {
        float s = rs[0] + rs[1] + rs[2] + rs[3];
        float t = rt[0] + rt[1] + rt[2] + rt[3];
        g_s[i] = s; g_Es[i] = expf(s); g_Fs[i] = expf(0.01f * s);
        g_t[i] = t; g_Et[i] = expf(t); g_Ft[i] = expf(0.01f * t);
    }
}

// ---------------- Kernel C: pipelined mma.sync tf32  P @ V ----------------
// P stored pair-packed: sP2f[buf][row][8*ks + 2*t4 + {0,1}] = P[row][8ks+t4], P[row][8ks+t4+4]
// -> A fragments load as LDS.64. Condition leaky sign via EsEt >= 1 (no g_t).
__global__ __launch_bounds__(256, 2) void k_mma(const int* __restrict__ adj) {
    extern __shared__ float smemf[];
    float (*sPb)[128][40]  = (float (*)[128][40])(smemf + SP_OFF);
    float (*sVb)[32][136]  = (float (*)[32][136])(smemf + SV_OFF);
    float* sDen            = smemf + DEN_OFF;
    const uint32_t sv_base = (uint32_t)__cvta_generic_to_shared(smemf + SV_OFF);

    const int tid = threadIdx.x;
    const int w   = tid >> 5;
    const int l   = tid & 31;
    const int g   = l >> 2;
    const int t4  = l & 3;
    const int rb  = blockIdx.x * MB;
    const int jsp = blockIdx.y;

    const int mrow = (w & 3) * 32;
    const int ncol = (w >> 2) * 64;

    const int r = tid >> 1;
    const int h = tid & 1;
    const float rowEs = g_Es[rb + r];
    const float rowFs = g_Fs[rb + r];
    const size_t adjrow = (size_t)(rb + r) * NN;

    float denreg = 0.f;

    float acc[2][8][4];
    #pragma unroll
    for (int m = 0; m < 2; m++)
        #pragma unroll
        for (int n = 0; n < 8; n++)
            #pragma unroll
            for (int i = 0; i < 4; i++) acc[m][n][i] = 0.f;

    const int jbase = jsp * JLEN;

    #define STAGE_V(jb_, buf_)                                                    \
        {                                                                         \
            _Pragma("unroll")                                                     \
            for (int it = 0; it < 4; ++it) {                                      \
                int f_ = tid + it * 256;                                          \
                int k_ = f_ >> 5, dq_ = f_ & 31;                                  \
                uint32_t dst_ = sv_base + (uint32_t)(((buf_) * 32 + k_) * 136 + 4 * dq_) * 4u; \
                cp_async16(dst_, g_Vr + (size_t)((jb_) + k_) * DD + 4 * dq_);     \
            }                                                                     \
            cp_commit();                                                          \
        }

    // Build 16 cols [16h, 16h+16) of row r; store pair-packed.
    #define BUILD_P(jb_, A4_, pb_)                                                \
        {                                                                         \
            float p_[16];                                                         \
            float psum_ = 0.f;                                                    \
            _Pragma("unroll")                                                     \
            for (int q_ = 0; q_ < 4; ++q_) {                                      \
                const int j_ = (jb_) + 16 * h + 4 * q_;                           \
                int4   av  = A4_[q_];                                             \
                float4 etv = *(const float4*)(g_Et + j_);                         \
                float4 ftv = *(const float4*)(g_Ft + j_);                         \
                float x_, y_, v_;                                                 \
                x_ = rowEs * etv.x; y_ = rowFs * ftv.x;                           \
                v_ = (av.x > 0) ? ((x_ >= 1.f) ? x_ : y_) : 0.f;                  \
                p_[4 * q_ + 0] = totf32(v_);                                      \
                x_ = rowEs * etv.y; y_ = rowFs * ftv.y;                           \
                v_ = (av.y > 0) ? ((x_ >= 1.f) ? x_ : y_) : 0.f;                  \
                p_[4 * q_ + 1] = totf32(v_);                                      \
                x_ = rowEs * etv.z; y_ = rowFs * ftv.z;                           \
                v_ = (av.z > 0) ? ((x_ >= 1.f) ? x_ : y_) : 0.f;                  \
                p_[4 * q_ + 2] = totf32(v_);                                      \
                x_ = rowEs * etv.w; y_ = rowFs * ftv.w;                           \
                v_ = (av.w > 0) ? ((x_ >= 1.f) ? x_ : y_) : 0.f;                  \
                p_[4 * q_ + 3] = totf32(v_);                                      \
                psum_ += (p_[4*q_+0] + p_[4*q_+1]) + (p_[4*q_+2] + p_[4*q_+3]);   \
            }                                                                     \
            float* rp_ = &sPb[pb_][r][16 * h];                                    \
            *(float4*)&rp_[0]  = make_float4(p_[0],  p_[4],  p_[1],  p_[5]);      \
            *(float4*)&rp_[4]  = make_float4(p_[2],  p_[6],  p_[3],  p_[7]);      \
            *(float4*)&rp_[8]  = make_float4(p_[8],  p_[12], p_[9],  p_[13]);     \
            *(float4*)&rp_[12] = make_float4(p_[10], p_[14], p_[11], p_[15]);     \
            psum_ += __shfl_down_sync(0xffffffffu, psum_, 1);                     \
            if (h == 0) denreg += psum_;                                          \
        }

    // ---- prologue: chunks 0 and 1 ----
    int4 a4[4];
    {
        STAGE_V(jbase, 0);
        #pragma unroll
        for (int q = 0; q < 4; ++q)
            a4[q] = *(const int4*)(adj + adjrow + jbase + 16 * h + 4 * q);
        BUILD_P(jbase, a4, 0);
        STAGE_V(jbase + KC, 1);
        #pragma unroll
        for (int q = 0; q < 4; ++q)
            a4[q] = *(const int4*)(adj + adjrow + jbase + KC + 16 * h + 4 * q);
        cp_wait0();
        __syncthreads();
    }

    for (int c = 0; c < NC; ++c) {
        const int buf = c & 1;

        // ---- overlapped build of P(c+1) ----
        if (c + 1 < NC) {
            BUILD_P(jbase + (c + 1) * KC, a4, buf ^ 1);
            if (c + 2 < NC) {
                if (w == 0) {
                    const int jn = jbase + (c + 2) * KC + 16 * h;
                    pf_l1(g_Et + jn); pf_l1(g_Ft + jn);
                }
                #pragma unroll
                for (int q = 0; q < 4; ++q)
                    a4[q] = *(const int4*)(adj + adjrow + jbase + (c + 2) * KC + 16 * h + 4 * q);
            }
        }

        // ---- MMA phase on chunk c ----
        #pragma unroll
        for (int ks = 0; ks < 4; ++ks) {
            const int k0 = 8 * ks;
            const int pk = 8 * ks + 2 * t4;   // float offset of (k0+t4, k0+t4+4) pair
            float afrag[2][4];
            #pragma unroll
            for (int m = 0; m < 2; ++m) {
                const int r0 = mrow + 16 * m;
                float2 alo = *(const float2*)&sPb[buf][r0 + g    ][pk];
                float2 ahi = *(const float2*)&sPb[buf][r0 + g + 8][pk];
                afrag[m][0] = alo.x; afrag[m][1] = ahi.x;
                afrag[m][2] = alo.y; afrag[m][3] = ahi.y;
            }
            #pragma unroll
            for (int n = 0; n < 8; ++n) {
                const int n0 = ncol + 8 * n;
                float bfrag[2];
                bfrag[0] = sVb[buf][k0 + t4    ][n0 + g];
                bfrag[1] = sVb[buf][k0 + t4 + 4][n0 + g];
                mma_tf32_16x8x8(acc[0][n], afrag[0], bfrag);
                mma_tf32_16x8x8(acc[1][n], afrag[1], bfrag);
            }
        }

        if (c + 1 < NC) {
            cp_wait0();
            __syncthreads();
            if (c + 2 < NC)
                STAGE_V(jbase + (c + 2) * KC, buf);
        }
    }

    // ---- epilogue ----
    float* outp = g_parts[jsp];
    #pragma unroll
    for (int m = 0; m < 2; ++m) {
        #pragma unroll
        for (int n = 0; n < 8; ++n) {
            const int row0 = rb + mrow + 16 * m + g;
            const int col  = ncol + 8 * n + 2 * t4;
            *(float2*)(outp + (size_t)row0 * DD + col) =
                make_float2(acc[m][n][0], acc[m][n][1]);
            *(float2*)(outp + (size_t)(row0 + 8) * DD + col) =
                make_float2(acc[m][n][2], acc[m][n][3]);
        }
    }
    __syncthreads();
    if (h == 0) sDen[r] = denreg;
    __syncthreads();
    if (tid < 128) g_dparts[jsp][rb + tid] = sDen[tid];
}

// ---------------- Kernel D: combine partials, normalize, relu ----------------
__global__ void k_final(float* __restrict__ out) {
    int idx = blockIdx.x * 256 + threadIdx.x;
    int r = idx >> 7;
    float dsum = g_dparts[0][r] + g_dparts[1][r] + g_dparts[2][r];
    float v = g_parts[0][idx] + g_parts[1][idx] + g_parts[2][idx];
    out[idx] = fmaxf(v / dsum, 0.f);
}

// ---------------- launch ----------------
extern "C" void kernel_launch(void* const* d_in, const int* in_sizes, int n_in,
                              void* d_out, int out_size) {
    const float* emb = (const float*)d_in[0];
    const int*   adj = (const int*)d_in[1];
    const float* W   = (const float*)d_in[2];
    const float* a   = (const float*)d_in[3];
    float* out = (float*)d_out;

    cudaFuncSetAttribute(k_mma, cudaFuncAttributeMaxDynamicSharedMemorySize, SMEM_BYTES);

    k_transW<<<(DD * DD + 255) / 256, 256>>>(W);
    k_enew<<<NN / 16, 256>>>(emb);
    k_scal<<<NN, 128>>>(a);
    k_mma<<<dim3(MBLK, JSPLIT), 256, SMEM_BYTES>>>(adj);
    k_final<<<(NN * DD) / 256, 256>>>(out);
}